// round 3
// baseline (speedup 1.0000x reference)
#include <cuda_runtime.h>
#include <cuda_bf16.h>
#include <cstdint>

// ============================================================================
// out[m] = 0.5 * sum_w max_{j<4}( x[m,:].W[4w+j,:] + b[4w+j] )
// x:[4096,4096]f32, W:[4096,4096]f32 (K-major), b:[4096] -> out:[4096]f32
//
// NOTE: harness PTX target is compute_100 (no 'a'): tcgen05 unavailable.
// Use baseline-PTX tensor path: mma.sync.m16n8k16 bf16 + ldmatrix + cp.async.
//
// k1: f32->bf16 convert into __device__ scratch
// k2: GEMM 256x128 CTA tile, BK=32, 5-stage cp.async pipeline, warp tile
//     64x64 (8 warps, 4x2), fused bias+maxpool4+rowsum -> per-(row,ntile)
// k3: reduce 32 partials/row, scale 0.5
// ============================================================================

__device__ __nv_bfloat16 g_xb[16777216];   // 32 MB
__device__ __nv_bfloat16 g_wb[16777216];   // 32 MB
__device__ float         g_part[131072];   // [4096 rows][32 n-tiles]

#define BM 256
#define BN 128
#define BK 32
#define ROW_BYTES 80u                       // 64B data + 16B pad (conflict-free)
#define A_TILE (BM * ROW_BYTES)             // 20480
#define B_TILE (BN * ROW_BYTES)             // 10240
#define STAGE  (A_TILE + B_TILE)            // 30720
#define NSTAGE 5
#define EPI_STRIDE 136                      // floats per row in epilogue smem
#define DYN_SMEM (NSTAGE * STAGE)           // 153600 (>= 256*136*4 = 139264)

static __device__ __forceinline__ uint32_t s2u(const void* p) {
    uint32_t a;
    asm volatile("{ .reg .u64 t; cvta.to.shared.u64 t, %1; cvt.u32.u64 %0, t; }"
                 : "=r"(a) : "l"(p));
    return a;
}
static __device__ __forceinline__ void cp16(uint32_t dst, const void* src) {
    asm volatile("cp.async.cg.shared.global [%0], [%1], 16;"
                 :: "r"(dst), "l"(src) : "memory");
}
static __device__ __forceinline__ void cp_commit() {
    asm volatile("cp.async.commit_group;" ::: "memory");
}
static __device__ __forceinline__ void ldsm4(uint32_t& r0, uint32_t& r1,
                                             uint32_t& r2, uint32_t& r3, uint32_t a) {
    asm volatile("ldmatrix.sync.aligned.m8n8.x4.shared.b16 {%0,%1,%2,%3}, [%4];"
                 : "=r"(r0), "=r"(r1), "=r"(r2), "=r"(r3) : "r"(a));
}
static __device__ __forceinline__ void mma16816(float* c, const uint32_t* a,
                                                uint32_t b0, uint32_t b1) {
    asm volatile("mma.sync.aligned.m16n8k16.row.col.f32.bf16.bf16.f32 "
                 "{%0,%1,%2,%3}, {%4,%5,%6,%7}, {%8,%9}, {%0,%1,%2,%3};"
                 : "+f"(c[0]), "+f"(c[1]), "+f"(c[2]), "+f"(c[3])
                 : "r"(a[0]), "r"(a[1]), "r"(a[2]), "r"(a[3]), "r"(b0), "r"(b1));
}

// ---------------- kernel 1: f32 -> bf16 convert ----------------
struct alignas(8) bf4 { __nv_bfloat162 a, b; };

__global__ __launch_bounds__(256) void convert_kernel(const float4* __restrict__ x,
                                                      const float4* __restrict__ w) {
    unsigned i = blockIdx.x * 256u + threadIdx.x;   // 8388608 total
    const unsigned HALF = 4194304u;
    float4 v;
    bf4* dst;
    if (i < HALF) {
        v = x[i];
        dst = reinterpret_cast<bf4*>(g_xb) + i;
    } else {
        v = w[i - HALF];
        dst = reinterpret_cast<bf4*>(g_wb) + (i - HALF);
    }
    bf4 o;
    o.a = __float22bfloat162_rn(make_float2(v.x, v.y));
    o.b = __float22bfloat162_rn(make_float2(v.z, v.w));
    *dst = o;
}

// ---------------- kernel 2: GEMM + fused epilogue ----------------
__global__ __launch_bounds__(256, 1) void gemm_pool_kernel(const float* __restrict__ bias) {
    extern __shared__ __align__(16) char dyn[];
    __shared__ float s_bias[BN];

    const int tid = threadIdx.x;
    const int lane = tid & 31;
    const int wid = tid >> 5;
    const int wm = wid & 3;          // 0..3 -> m offset wm*64
    const int wn = wid >> 2;         // 0..1 -> n offset wn*64
    const int m0 = blockIdx.y * BM;
    const int n0 = blockIdx.x * BN;

    const uint32_t smem0 = s2u(dyn);

    if (tid < BN) s_bias[tid] = bias[n0 + tid];

    // ---- cp.async geometry: thread t loads A row t (4x16B) + B row t&127 (2x16B)
    const char* gA = (const char*)(g_xb + (size_t)(m0 + tid) * 4096);
    const char* gB = (const char*)(g_wb + (size_t)(n0 + (tid & 127)) * 4096);
    const uint32_t bc16 = (uint32_t)(tid >> 7) * 2;   // 0 or 2
    const uint32_t aDst = smem0 + (uint32_t)tid * ROW_BYTES;
    const uint32_t bDst = smem0 + A_TILE + (uint32_t)(tid & 127) * ROW_BYTES + bc16 * 16u;

#define LOAD_CHUNK(i, s) do {                                                  \
        uint32_t _as = aDst + (uint32_t)(s) * STAGE;                           \
        uint32_t _bs = bDst + (uint32_t)(s) * STAGE;                           \
        const char* _ga = gA + (size_t)(i) * 64;                               \
        const char* _gb = gB + (size_t)(i) * 64;                               \
        cp16(_as,       _ga);                                                  \
        cp16(_as + 16u, _ga + 16);                                             \
        cp16(_as + 32u, _ga + 32);                                             \
        cp16(_as + 48u, _ga + 48);                                             \
        cp16(_bs,       _gb + bc16 * 16);                                      \
        cp16(_bs + 16u, _gb + bc16 * 16 + 16);                                 \
        cp_commit();                                                           \
    } while (0)

    // ---- ldmatrix base addresses (stage-relative)
    uint32_t aAddr[4], bAddr[4];
    {
        const int arow = (lane & 15);
        const int acol = (lane >> 4);          // 0/1 -> 16B half
        #pragma unroll
        for (int mi = 0; mi < 4; mi++)
            aAddr[mi] = smem0 + (uint32_t)((wm * 64 + mi * 16 + arow) * ROW_BYTES)
                        + (uint32_t)acol * 16u;
        const int brow = (lane & 7) + ((lane >> 4) << 3);
        const int bcol = (lane >> 3) & 1;
        #pragma unroll
        for (int nj = 0; nj < 4; nj++)
            bAddr[nj] = smem0 + A_TILE + (uint32_t)((wn * 64 + nj * 16 + brow) * ROW_BYTES)
                        + (uint32_t)bcol * 16u;
    }

    float acc[4][8][4];
    #pragma unroll
    for (int mi = 0; mi < 4; mi++)
        #pragma unroll
        for (int ni = 0; ni < 8; ni++)
            #pragma unroll
            for (int k = 0; k < 4; k++) acc[mi][ni][k] = 0.0f;

    // ---- prologue: 4 stages in flight
    LOAD_CHUNK(0, 0);
    LOAD_CHUNK(1, 1);
    LOAD_CHUNK(2, 2);
    LOAD_CHUNK(3, 3);

    int s = 0;
    #pragma unroll 1
    for (int i = 0; i < 128; i++) {
        asm volatile("cp.async.wait_group 3;" ::: "memory");
        __syncthreads();

        // issue chunk i+4 into stage (i+4)%5 (safe: all threads past compute i-1)
        if (i < 124) {
            int sp = s + 4;
            if (sp >= NSTAGE) sp -= NSTAGE;
            LOAD_CHUNK(i + 4, sp);
        } else {
            cp_commit();   // empty group keeps wait_group accounting exact
        }

        // compute stage s (two k16 steps)
        const uint32_t so = (uint32_t)s * STAGE;
        #pragma unroll
        for (int ks = 0; ks < 2; ks++) {
            uint32_t a[4][4], b[4][4];
            #pragma unroll
            for (int mi = 0; mi < 4; mi++)
                ldsm4(a[mi][0], a[mi][1], a[mi][2], a[mi][3],
                      aAddr[mi] + so + (uint32_t)ks * 32u);
            #pragma unroll
            for (int nj = 0; nj < 4; nj++)
                ldsm4(b[nj][0], b[nj][1], b[nj][2], b[nj][3],
                      bAddr[nj] + so + (uint32_t)ks * 32u);
            #pragma unroll
            for (int mi = 0; mi < 4; mi++)
                #pragma unroll
                for (int ni = 0; ni < 8; ni++)
                    mma16816(acc[mi][ni], a[mi], b[ni >> 1][(ni & 1) * 2],
                             b[ni >> 1][(ni & 1) * 2 + 1]);
        }
        s = (s == NSTAGE - 1) ? 0 : s + 1;
    }
    __syncthreads();   // all compute done before smem reuse

    // ---- epilogue: accum -> smem [256][EPI_STRIDE]
    #pragma unroll
    for (int mi = 0; mi < 4; mi++)
        #pragma unroll
        for (int ni = 0; ni < 8; ni++)
            #pragma unroll
            for (int h = 0; h < 2; h++) {
                int row = wm * 64 + mi * 16 + (lane >> 2) + h * 8;
                int col = wn * 64 + ni * 8 + (lane & 3) * 2;
                float2 v = make_float2(acc[mi][ni][h * 2], acc[mi][ni][h * 2 + 1]);
                *reinterpret_cast<float2*>(dyn + ((size_t)row * EPI_STRIDE + col) * 4) = v;
            }
    __syncthreads();

    // ---- per-row bias + maxpool4 + sum
    {
        const int r = tid;   // 0..255
        const float* rp = reinterpret_cast<const float*>(dyn) + (size_t)r * EPI_STRIDE;
        float sum = 0.0f;
        #pragma unroll
        for (int w = 0; w < 32; w++) {
            float4 v = *reinterpret_cast<const float4*>(rp + w * 4);
            float m01 = fmaxf(v.x + s_bias[w * 4 + 0], v.y + s_bias[w * 4 + 1]);
            float m23 = fmaxf(v.z + s_bias[w * 4 + 2], v.w + s_bias[w * 4 + 3]);
            sum += fmaxf(m01, m23);
        }
        g_part[(size_t)(m0 + r) * 32 + blockIdx.x] = sum;
    }
}

// ---------------- kernel 3: reduce 32 partials per row ----------------
__global__ __launch_bounds__(256) void reduce_kernel(float* __restrict__ out) {
    int r = blockIdx.x * 256 + threadIdx.x;
    const float4* p = reinterpret_cast<const float4*>(&g_part[(size_t)r * 32]);
    float s = 0.0f;
    #pragma unroll
    for (int i = 0; i < 8; i++) {
        float4 v = p[i];
        s += (v.x + v.y) + (v.z + v.w);
    }
    out[r] = 0.5f * s;
}

// ---------------- launch ----------------
extern "C" void kernel_launch(void* const* d_in, const int* in_sizes, int n_in,
                              void* d_out, int out_size) {
    const float4* x = (const float4*)d_in[0];
    const float4* w = (const float4*)d_in[1];
    const float*  b = (const float*)d_in[2];
    float* out = (float*)d_out;

    cudaFuncSetAttribute(gemm_pool_kernel,
                         cudaFuncAttributeMaxDynamicSharedMemorySize, DYN_SMEM);

    convert_kernel<<<32768, 256>>>(x, w);
    gemm_pool_kernel<<<dim3(32, 16), 256, DYN_SMEM>>>(b);
    reduce_kernel<<<16, 256>>>(out);
}

// round 4
// speedup vs baseline: 1.0186x; 1.0186x over previous
#include <cuda_runtime.h>
#include <cuda_bf16.h>
#include <cstdint>

// ============================================================================
// out[m] = 0.5 * sum_w max_{j<4}( x[m,:].W[4w+j,:] + b[4w+j] )
// x:[4096,4096]f32, W:[4096,4096]f32 (K-major), b:[4096] -> out:[4096]f32
//
// compute_100 PTX target => no tcgen05; mma.sync.m16n8k16 bf16 path.
// R4 changes vs R3: XOR-swizzled 128B rows (kills 4-way cp.async store
// conflicts), BK=64 (half the loop iterations/syncs), 4-stage pipeline.
// ============================================================================

__device__ __nv_bfloat16 g_xb[16777216];   // 32 MB
__device__ __nv_bfloat16 g_wb[16777216];   // 32 MB
__device__ float         g_part[131072];   // [4096 rows][32 n-tiles]

#define BM 256
#define BN 128
#define BK 64
#define ROW_BYTES 128u
#define A_TILE (BM * ROW_BYTES)             // 32768
#define B_TILE (BN * ROW_BYTES)             // 16384
#define STAGE  (A_TILE + B_TILE)            // 49152
#define NSTAGE 4
#define EPI_STRIDE 136
#define DYN_SMEM (NSTAGE * STAGE)           // 196608

static __device__ __forceinline__ uint32_t s2u(const void* p) {
    uint32_t a;
    asm volatile("{ .reg .u64 t; cvta.to.shared.u64 t, %1; cvt.u32.u64 %0, t; }"
                 : "=r"(a) : "l"(p));
    return a;
}
static __device__ __forceinline__ void cp16(uint32_t dst, const void* src) {
    asm volatile("cp.async.cg.shared.global [%0], [%1], 16;"
                 :: "r"(dst), "l"(src) : "memory");
}
static __device__ __forceinline__ void cp_commit() {
    asm volatile("cp.async.commit_group;" ::: "memory");
}
static __device__ __forceinline__ void ldsm4(uint32_t& r0, uint32_t& r1,
                                             uint32_t& r2, uint32_t& r3, uint32_t a) {
    asm volatile("ldmatrix.sync.aligned.m8n8.x4.shared.b16 {%0,%1,%2,%3}, [%4];"
                 : "=r"(r0), "=r"(r1), "=r"(r2), "=r"(r3) : "r"(a));
}
static __device__ __forceinline__ void mma16816(float* c, const uint32_t* a,
                                                uint32_t b0, uint32_t b1) {
    asm volatile("mma.sync.aligned.m16n8k16.row.col.f32.bf16.bf16.f32 "
                 "{%0,%1,%2,%3}, {%4,%5,%6,%7}, {%8,%9}, {%0,%1,%2,%3};"
                 : "+f"(c[0]), "+f"(c[1]), "+f"(c[2]), "+f"(c[3])
                 : "r"(a[0]), "r"(a[1]), "r"(a[2]), "r"(a[3]), "r"(b0), "r"(b1));
}

// ---------------- kernel 1: f32 -> bf16 convert ----------------
struct alignas(8) bf4 { __nv_bfloat162 a, b; };

__global__ __launch_bounds__(256) void convert_kernel(const float4* __restrict__ x,
                                                      const float4* __restrict__ w) {
    unsigned i = blockIdx.x * 256u + threadIdx.x;   // 8388608 total
    const unsigned HALF = 4194304u;
    float4 v;
    bf4* dst;
    if (i < HALF) {
        v = x[i];
        dst = reinterpret_cast<bf4*>(g_xb) + i;
    } else {
        v = w[i - HALF];
        dst = reinterpret_cast<bf4*>(g_wb) + (i - HALF);
    }
    bf4 o;
    o.a = __float22bfloat162_rn(make_float2(v.x, v.y));
    o.b = __float22bfloat162_rn(make_float2(v.z, v.w));
    *dst = o;
}

// ---------------- kernel 2: GEMM + fused epilogue ----------------
__global__ __launch_bounds__(256, 1) void gemm_pool_kernel(const float* __restrict__ bias) {
    extern __shared__ __align__(16) char dyn[];
    __shared__ float s_bias[BN];

    const int tid = threadIdx.x;
    const int lane = tid & 31;
    const int wid = tid >> 5;
    const int wm = wid & 3;          // m offset wm*64
    const int wn = wid >> 2;         // n offset wn*64
    const int m0 = blockIdx.y * BM;
    const int n0 = blockIdx.x * BN;

    const uint32_t smem0 = s2u(dyn);

    if (tid < BN) s_bias[tid] = bias[n0 + tid];

    // ---- cp.async geometry (XOR swizzle: chunk' = chunk ^ (row&7), 16B chunks)
    // A: thread t owns row t (8 chunks). B: thread t owns row t&127, half t>>7.
    const char* gA = (const char*)(g_xb + (size_t)(m0 + tid) * 4096);
    const char* gB = (const char*)(g_wb + (size_t)(n0 + (tid & 127)) * 4096);
    const uint32_t ax = (uint32_t)(tid & 7);
    const uint32_t bh = (uint32_t)(tid >> 7) * 4u;   // starting chunk for B half
    const uint32_t aRow = smem0 + (uint32_t)tid * ROW_BYTES;
    const uint32_t bRow = smem0 + A_TILE + (uint32_t)(tid & 127) * ROW_BYTES;

#define LOAD_CHUNK(i, s) do {                                                  \
        uint32_t _as = aRow + (uint32_t)(s) * STAGE;                           \
        uint32_t _bs = bRow + (uint32_t)(s) * STAGE;                           \
        const char* _ga = gA + (size_t)(i) * 128;                              \
        const char* _gb = gB + (size_t)(i) * 128;                              \
        _Pragma("unroll")                                                      \
        for (uint32_t c = 0; c < 8; c++)                                       \
            cp16(_as + ((c ^ ax) << 4), _ga + c * 16);                         \
        _Pragma("unroll")                                                      \
        for (uint32_t c = 0; c < 4; c++)                                       \
            cp16(_bs + (((bh + c) ^ ax) << 4), _gb + (bh + c) * 16);           \
        cp_commit();                                                           \
    } while (0)

    // ---- ldmatrix bases (swizzle offsets precomputed per k16 step)
    uint32_t aAddr[4], bAddr[4], kOffA[4], kOffB[4];
    {
        const uint32_t al7 = (uint32_t)(lane & 7);
        const uint32_t ahi = (uint32_t)(lane >> 4);          // A 16B-half select
        const uint32_t bcol = (uint32_t)((lane >> 3) & 1);   // B 16B-half select
        const int arow = (lane & 15);
        const int brow = (lane & 7) + ((lane >> 4) << 3);
        #pragma unroll
        for (int mi = 0; mi < 4; mi++)
            aAddr[mi] = smem0 + (uint32_t)((wm * 64 + mi * 16 + arow) * ROW_BYTES);
        #pragma unroll
        for (int nj = 0; nj < 4; nj++)
            bAddr[nj] = smem0 + A_TILE
                        + (uint32_t)((wn * 64 + nj * 16 + brow) * ROW_BYTES);
        #pragma unroll
        for (uint32_t ks = 0; ks < 4; ks++) {
            kOffA[ks] = ((2u * ks + ahi) ^ al7) << 4;
            kOffB[ks] = ((2u * ks + bcol) ^ al7) << 4;
        }
    }

    float acc[4][8][4];
    #pragma unroll
    for (int mi = 0; mi < 4; mi++)
        #pragma unroll
        for (int ni = 0; ni < 8; ni++)
            #pragma unroll
            for (int k = 0; k < 4; k++) acc[mi][ni][k] = 0.0f;

    // ---- prologue: 3 stages in flight
    LOAD_CHUNK(0, 0);
    LOAD_CHUNK(1, 1);
    LOAD_CHUNK(2, 2);

    #pragma unroll 1
    for (int i = 0; i < 64; i++) {
        asm volatile("cp.async.wait_group 2;" ::: "memory");
        __syncthreads();

        if (i < 61) {
            LOAD_CHUNK(i + 3, (i + 3) & 3);
        } else {
            cp_commit();   // keep wait_group accounting exact
        }

        const uint32_t so = (uint32_t)(i & 3) * STAGE;
        #pragma unroll
        for (int ks = 0; ks < 4; ks++) {
            uint32_t a[4][4], b[4][4];
            #pragma unroll
            for (int mi = 0; mi < 4; mi++)
                ldsm4(a[mi][0], a[mi][1], a[mi][2], a[mi][3],
                      aAddr[mi] + so + kOffA[ks]);
            #pragma unroll
            for (int nj = 0; nj < 4; nj++)
                ldsm4(b[nj][0], b[nj][1], b[nj][2], b[nj][3],
                      bAddr[nj] + so + kOffB[ks]);
            #pragma unroll
            for (int mi = 0; mi < 4; mi++)
                #pragma unroll
                for (int ni = 0; ni < 8; ni++)
                    mma16816(acc[mi][ni], a[mi], b[ni >> 1][(ni & 1) * 2],
                             b[ni >> 1][(ni & 1) * 2 + 1]);
        }
    }
    __syncthreads();   // all compute done before smem reuse

    // ---- epilogue: accum -> smem [256][EPI_STRIDE]
    #pragma unroll
    for (int mi = 0; mi < 4; mi++)
        #pragma unroll
        for (int ni = 0; ni < 8; ni++)
            #pragma unroll
            for (int h = 0; h < 2; h++) {
                int row = wm * 64 + mi * 16 + (lane >> 2) + h * 8;
                int col = wn * 64 + ni * 8 + (lane & 3) * 2;
                float2 v = make_float2(acc[mi][ni][h * 2], acc[mi][ni][h * 2 + 1]);
                *reinterpret_cast<float2*>(dyn + ((size_t)row * EPI_STRIDE + col) * 4) = v;
            }
    __syncthreads();

    // ---- per-row bias + maxpool4 + sum
    {
        const int r = tid;
        const float* rp = reinterpret_cast<const float*>(dyn) + (size_t)r * EPI_STRIDE;
        float sum = 0.0f;
        #pragma unroll
        for (int w = 0; w < 32; w++) {
            float4 v = *reinterpret_cast<const float4*>(rp + w * 4);
            float m01 = fmaxf(v.x + s_bias[w * 4 + 0], v.y + s_bias[w * 4 + 1]);
            float m23 = fmaxf(v.z + s_bias[w * 4 + 2], v.w + s_bias[w * 4 + 3]);
            sum += fmaxf(m01, m23);
        }
        g_part[(size_t)(m0 + r) * 32 + blockIdx.x] = sum;
    }
}

// ---------------- kernel 3: reduce 32 partials per row ----------------
__global__ __launch_bounds__(256) void reduce_kernel(float* __restrict__ out) {
    int r = blockIdx.x * 256 + threadIdx.x;
    const float4* p = reinterpret_cast<const float4*>(&g_part[(size_t)r * 32]);
    float s = 0.0f;
    #pragma unroll
    for (int i = 0; i < 8; i++) {
        float4 v = p[i];
        s += (v.x + v.y) + (v.z + v.w);
    }
    out[r] = 0.5f * s;
}

// ---------------- launch ----------------
extern "C" void kernel_launch(void* const* d_in, const int* in_sizes, int n_in,
                              void* d_out, int out_size) {
    const float4* x = (const float4*)d_in[0];
    const float4* w = (const float4*)d_in[1];
    const float*  b = (const float*)d_in[2];
    float* out = (float*)d_out;

    cudaFuncSetAttribute(gemm_pool_kernel,
                         cudaFuncAttributeMaxDynamicSharedMemorySize, DYN_SMEM);

    convert_kernel<<<32768, 256>>>(x, w);
    gemm_pool_kernel<<<dim3(32, 16), 256, DYN_SMEM>>>(b);
    reduce_kernel<<<16, 256>>>(out);
}

// round 6
// speedup vs baseline: 1.5120x; 1.4843x over previous
#include <cuda_runtime.h>
#include <cuda_bf16.h>
#include <cstdint>

// ============================================================================
// out[m] = 0.5 * sum_w max_{j<4}( x[m,:].W[4w+j,:] + b[4w+j] )
// compute_100 PTX => legacy mma.sync.m16n8k16 bf16 path (no tcgen05).
//
// R6 == R5 re-bench (R5 bench died to container-infra failure, kernel never
// measured): 512-thread CTAs (4 warps/SMSP for latency hiding), 16 warps in
// 4x4 grid, 64x32 warp tile (64 acc regs -> no spills at 128 reg cap),
// shuffle-based fused epilogue (no big smem transpose), 4-stage pipeline.
// ============================================================================

__device__ __nv_bfloat16 g_xb[16777216];   // 32 MB
__device__ __nv_bfloat16 g_wb[16777216];   // 32 MB
__device__ float         g_part[131072];   // [4096 rows][32 n-tiles]

#define BM 256
#define BN 128
#define BK 64
#define ROW_BYTES 128u
#define A_TILE (BM * ROW_BYTES)             // 32768
#define B_TILE (BN * ROW_BYTES)             // 16384
#define STAGE  (A_TILE + B_TILE)            // 49152
#define NSTAGE 4
#define DYN_SMEM (NSTAGE * STAGE)           // 196608

static __device__ __forceinline__ uint32_t s2u(const void* p) {
    uint32_t a;
    asm volatile("{ .reg .u64 t; cvta.to.shared.u64 t, %1; cvt.u32.u64 %0, t; }"
                 : "=r"(a) : "l"(p));
    return a;
}
static __device__ __forceinline__ void cp16(uint32_t dst, const void* src) {
    asm volatile("cp.async.cg.shared.global [%0], [%1], 16;"
                 :: "r"(dst), "l"(src) : "memory");
}
static __device__ __forceinline__ void cp_commit() {
    asm volatile("cp.async.commit_group;" ::: "memory");
}
static __device__ __forceinline__ void ldsm4(uint32_t& r0, uint32_t& r1,
                                             uint32_t& r2, uint32_t& r3, uint32_t a) {
    asm volatile("ldmatrix.sync.aligned.m8n8.x4.shared.b16 {%0,%1,%2,%3}, [%4];"
                 : "=r"(r0), "=r"(r1), "=r"(r2), "=r"(r3) : "r"(a));
}
static __device__ __forceinline__ void mma16816(float* c, const uint32_t* a,
                                                uint32_t b0, uint32_t b1) {
    asm volatile("mma.sync.aligned.m16n8k16.row.col.f32.bf16.bf16.f32 "
                 "{%0,%1,%2,%3}, {%4,%5,%6,%7}, {%8,%9}, {%0,%1,%2,%3};"
                 : "+f"(c[0]), "+f"(c[1]), "+f"(c[2]), "+f"(c[3])
                 : "r"(a[0]), "r"(a[1]), "r"(a[2]), "r"(a[3]), "r"(b0), "r"(b1));
}

// ---------------- kernel 1: f32 -> bf16 convert ----------------
struct alignas(8) bf4 { __nv_bfloat162 a, b; };

__global__ __launch_bounds__(256) void convert_kernel(const float4* __restrict__ x,
                                                      const float4* __restrict__ w) {
    unsigned i = blockIdx.x * 256u + threadIdx.x;
    const unsigned HALF = 4194304u;
    float4 v;
    bf4* dst;
    if (i < HALF) {
        v = x[i];
        dst = reinterpret_cast<bf4*>(g_xb) + i;
    } else {
        v = w[i - HALF];
        dst = reinterpret_cast<bf4*>(g_wb) + (i - HALF);
    }
    bf4 o;
    o.a = __float22bfloat162_rn(make_float2(v.x, v.y));
    o.b = __float22bfloat162_rn(make_float2(v.z, v.w));
    *dst = o;
}

// ---------------- kernel 2: GEMM + fused epilogue ----------------
__global__ __launch_bounds__(512, 1) void gemm_pool_kernel(const float* __restrict__ bias) {
    extern __shared__ __align__(16) char dyn[];
    __shared__ float s_bias[BN];
    __shared__ float s_part[BM][4];

    const int tid = threadIdx.x;
    const int lane = tid & 31;
    const int wid = tid >> 5;           // 0..15
    const int wm = wid >> 2;            // 0..3 -> m offset wm*64
    const int wn = wid & 3;             // 0..3 -> n offset wn*32
    const int m0 = blockIdx.y * BM;
    const int n0 = blockIdx.x * BN;

    const uint32_t smem0 = s2u(dyn);

    if (tid < BN) s_bias[tid] = bias[n0 + tid];

    // ---- cp.async geometry (XOR swizzle: slot = chunk ^ (row&7), 16B chunks)
    // A: thread t -> row t>>1 (4 chunks, base (t&1)*4). B: row t>>2 (2 chunks).
    const int  aR  = tid >> 1;
    const int  bR  = tid >> 2;
    const uint32_t aC = (uint32_t)(tid & 1) * 4u;
    const uint32_t bC = (uint32_t)(tid & 3) * 2u;
    const uint32_t ax = (uint32_t)(aR & 7);
    const uint32_t bx = (uint32_t)(bR & 7);
    const char* gA = (const char*)(g_xb + (size_t)(m0 + aR) * 4096);
    const char* gB = (const char*)(g_wb + (size_t)(n0 + bR) * 4096);
    const uint32_t aRow = smem0 + (uint32_t)aR * ROW_BYTES;
    const uint32_t bRow = smem0 + A_TILE + (uint32_t)bR * ROW_BYTES;

#define LOAD_CHUNK(i, s) do {                                                  \
        uint32_t _as = aRow + (uint32_t)(s) * STAGE;                           \
        uint32_t _bs = bRow + (uint32_t)(s) * STAGE;                           \
        const char* _ga = gA + (size_t)(i) * 128;                              \
        const char* _gb = gB + (size_t)(i) * 128;                              \
        _Pragma("unroll")                                                      \
        for (uint32_t c = 0; c < 4; c++)                                       \
            cp16(_as + (((aC + c) ^ ax) << 4), _ga + (aC + c) * 16);           \
        _Pragma("unroll")                                                      \
        for (uint32_t c = 0; c < 2; c++)                                       \
            cp16(_bs + (((bC + c) ^ bx) << 4), _gb + (bC + c) * 16);           \
        cp_commit();                                                           \
    } while (0)

    // ---- ldmatrix bases (swizzle offsets per k16 step)
    uint32_t aAddr[4], bAddr[2], kOffA[4], kOffB[4];
    {
        const uint32_t al7 = (uint32_t)(lane & 7);
        const uint32_t ahi = (uint32_t)(lane >> 4);
        const uint32_t bcol = (uint32_t)((lane >> 3) & 1);
        const int arow = (lane & 15);
        const int brow = (lane & 7) + ((lane >> 4) << 3);
        #pragma unroll
        for (int mi = 0; mi < 4; mi++)
            aAddr[mi] = smem0 + (uint32_t)((wm * 64 + mi * 16 + arow) * ROW_BYTES);
        #pragma unroll
        for (int nj = 0; nj < 2; nj++)
            bAddr[nj] = smem0 + A_TILE
                        + (uint32_t)((wn * 32 + nj * 16 + brow) * ROW_BYTES);
        #pragma unroll
        for (uint32_t ks = 0; ks < 4; ks++) {
            kOffA[ks] = ((2u * ks + ahi) ^ al7) << 4;
            kOffB[ks] = ((2u * ks + bcol) ^ al7) << 4;
        }
    }

    float acc[4][4][4];
    #pragma unroll
    for (int mi = 0; mi < 4; mi++)
        #pragma unroll
        for (int ni = 0; ni < 4; ni++)
            #pragma unroll
            for (int k = 0; k < 4; k++) acc[mi][ni][k] = 0.0f;

    // ---- prologue: 3 stages in flight
    LOAD_CHUNK(0, 0);
    LOAD_CHUNK(1, 1);
    LOAD_CHUNK(2, 2);

    #pragma unroll 1
    for (int i = 0; i < 64; i++) {
        asm volatile("cp.async.wait_group 2;" ::: "memory");
        __syncthreads();

        if (i < 61) {
            LOAD_CHUNK(i + 3, (i + 3) & 3);   // stage != computing stage (i&3)
        } else {
            cp_commit();
        }

        const uint32_t so = (uint32_t)(i & 3) * STAGE;
        #pragma unroll
        for (int ks = 0; ks < 4; ks++) {
            uint32_t a[4][4], b[2][4];
            #pragma unroll
            for (int mi = 0; mi < 4; mi++)
                ldsm4(a[mi][0], a[mi][1], a[mi][2], a[mi][3],
                      aAddr[mi] + so + kOffA[ks]);
            #pragma unroll
            for (int nj = 0; nj < 2; nj++)
                ldsm4(b[nj][0], b[nj][1], b[nj][2], b[nj][3],
                      bAddr[nj] + so + kOffB[ks]);
            #pragma unroll
            for (int mi = 0; mi < 4; mi++)
                #pragma unroll
                for (int ni = 0; ni < 4; ni++)
                    mma16816(acc[mi][ni], a[mi], b[ni >> 1][(ni & 1) * 2],
                             b[ni >> 1][(ni & 1) * 2 + 1]);
        }
    }

    // ---- fused epilogue: bias + maxpool4 + row-sum via shuffles ----
    // acc[mi][ni][h*2+c] = row (wm*64+mi*16+(lane>>2)+h*8),
    //                      col (wn*32+ni*8+(lane&3)*2+c)
    {
        const int q = lane & 3;
        #pragma unroll
        for (int mi = 0; mi < 4; mi++)
            #pragma unroll
            for (int h = 0; h < 2; h++) {
                float s = 0.0f;
                #pragma unroll
                for (int ni = 0; ni < 4; ni++) {
                    const int c0 = wn * 32 + ni * 8 + q * 2;
                    float v0 = acc[mi][ni][h * 2 + 0] + s_bias[c0 + 0];
                    float v1 = acc[mi][ni][h * 2 + 1] + s_bias[c0 + 1];
                    float pm = fmaxf(v0, v1);
                    pm = fmaxf(pm, __shfl_xor_sync(0xFFFFFFFFu, pm, 1));
                    s += pm;                     // window (parity (q>>1)) of ni
                }
                s += __shfl_xor_sync(0xFFFFFFFFu, s, 2);   // other parity
                if (q == 0)
                    s_part[wm * 64 + mi * 16 + (lane >> 2) + h * 8][wn] = s;
            }
    }
    __syncthreads();
    if (tid < BM) {
        float4 v = *reinterpret_cast<const float4*>(&s_part[tid][0]);
        g_part[(size_t)(m0 + tid) * 32 + blockIdx.x] = (v.x + v.y) + (v.z + v.w);
    }
}

// ---------------- kernel 3: reduce 32 partials per row ----------------
__global__ __launch_bounds__(256) void reduce_kernel(float* __restrict__ out) {
    int r = blockIdx.x * 256 + threadIdx.x;
    const float4* p = reinterpret_cast<const float4*>(&g_part[(size_t)r * 32]);
    float s = 0.0f;
    #pragma unroll
    for (int i = 0; i < 8; i++) {
        float4 v = p[i];
        s += (v.x + v.y) + (v.z + v.w);
    }
    out[r] = 0.5f * s;
}

// ---------------- launch ----------------
extern "C" void kernel_launch(void* const* d_in, const int* in_sizes, int n_in,
                              void* d_out, int out_size) {
    const float4* x = (const float4*)d_in[0];
    const float4* w = (const float4*)d_in[1];
    const float*  b = (const float*)d_in[2];
    float* out = (float*)d_out;

    cudaFuncSetAttribute(gemm_pool_kernel,
                         cudaFuncAttributeMaxDynamicSharedMemorySize, DYN_SMEM);

    convert_kernel<<<32768, 256>>>(x, w);
    gemm_pool_kernel<<<dim3(32, 16), 512, DYN_SMEM>>>(b);
    reduce_kernel<<<16, 256>>>(out);
}

// round 7
// speedup vs baseline: 2.8991x; 1.9174x over previous
#include <cuda_runtime.h>
#include <cstdint>

// ============================================================================
// out[m] = 0.5 * sum_w max_{j<4}( x[m,:].W[4w+j,:] + b[4w+j] )
// compute_100 PTX => legacy mma.sync only. R6 established bf16 HMMA pipe
// saturated (~512 MAC/cyc/SM, 96%). R7: int8 IMMA m16n8k32 with per-row
// scales: byte-identical fragments/smem layout, half the iterations.
//
// k1: per-row absmax quantize x,W -> int8 + f32 scales
// k2: IMMA GEMM 256x128 tile, 512 thr, 16 warps 4x4 (64x32 warp tiles),
//     K chunk 128 (32 iters), 4-stage cp.async, fused scale+bias+pool+sum
// k3: reduce 32 partials/row
// ============================================================================

__device__ int8_t g_x8[16777216];   // 16 MB
__device__ int8_t g_w8[16777216];   // 16 MB
__device__ float  g_sx[4096];
__device__ float  g_sw[4096];
__device__ float  g_part[131072];   // [4096 rows][32 n-tiles]

#define BM 256
#define BN 128
#define ROW_BYTES 128u
#define A_TILE (BM * ROW_BYTES)             // 32768
#define B_TILE (BN * ROW_BYTES)             // 16384
#define STAGE  (A_TILE + B_TILE)            // 49152
#define NSTAGE 4
#define DYN_SMEM (NSTAGE * STAGE)           // 196608
#define NITER 32                            // 4096 / 128

static __device__ __forceinline__ uint32_t s2u(const void* p) {
    uint32_t a;
    asm volatile("{ .reg .u64 t; cvta.to.shared.u64 t, %1; cvt.u32.u64 %0, t; }"
                 : "=r"(a) : "l"(p));
    return a;
}
static __device__ __forceinline__ void cp16(uint32_t dst, const void* src) {
    asm volatile("cp.async.cg.shared.global [%0], [%1], 16;"
                 :: "r"(dst), "l"(src) : "memory");
}
static __device__ __forceinline__ void cp_commit() {
    asm volatile("cp.async.commit_group;" ::: "memory");
}
static __device__ __forceinline__ void ldsm4(uint32_t& r0, uint32_t& r1,
                                             uint32_t& r2, uint32_t& r3, uint32_t a) {
    asm volatile("ldmatrix.sync.aligned.m8n8.x4.shared.b16 {%0,%1,%2,%3}, [%4];"
                 : "=r"(r0), "=r"(r1), "=r"(r2), "=r"(r3) : "r"(a));
}
static __device__ __forceinline__ void imma16832(int* c, const uint32_t* a,
                                                 uint32_t b0, uint32_t b1) {
    asm volatile("mma.sync.aligned.m16n8k32.row.col.s32.s8.s8.s32 "
                 "{%0,%1,%2,%3}, {%4,%5,%6,%7}, {%8,%9}, {%0,%1,%2,%3};"
                 : "+r"(c[0]), "+r"(c[1]), "+r"(c[2]), "+r"(c[3])
                 : "r"(a[0]), "r"(a[1]), "r"(a[2]), "r"(a[3]), "r"(b0), "r"(b1));
}

// ---------------- kernel 1: per-row absmax quantize ----------------
__global__ __launch_bounds__(256) void quantize_kernel(const float4* __restrict__ x,
                                                       const float4* __restrict__ w) {
    __shared__ float s_red[8];
    const int r = blockIdx.x;          // 0..8191: 0-4095 = x rows, rest = W rows
    const bool isx = r < 4096;
    const int rr = isx ? r : r - 4096;
    const float4* src = (isx ? x : w) + (size_t)rr * 1024;

    float4 v[4];
    float amax = 0.0f;
    #pragma unroll
    for (int j = 0; j < 4; j++) {
        v[j] = src[threadIdx.x + 256 * j];
        amax = fmaxf(amax, fmaxf(fmaxf(fabsf(v[j].x), fabsf(v[j].y)),
                                 fmaxf(fabsf(v[j].z), fabsf(v[j].w))));
    }
    #pragma unroll
    for (int o = 16; o; o >>= 1)
        amax = fmaxf(amax, __shfl_xor_sync(0xFFFFFFFFu, amax, o));
    if ((threadIdx.x & 31) == 0) s_red[threadIdx.x >> 5] = amax;
    __syncthreads();
    if (threadIdx.x < 32) {
        float m = (threadIdx.x < 8) ? s_red[threadIdx.x] : 0.0f;
        #pragma unroll
        for (int o = 4; o; o >>= 1)
            m = fmaxf(m, __shfl_xor_sync(0xFFFFFFFFu, m, o));
        if (threadIdx.x == 0) s_red[0] = m;
    }
    __syncthreads();
    const float smax = fmaxf(s_red[0], 1e-20f);
    const float inv = 127.0f / smax;
    if (threadIdx.x == 0) {
        if (isx) g_sx[rr] = smax * (1.0f / 127.0f);
        else     g_sw[rr] = smax * (1.0f / 127.0f);
    }
    char4* dst = reinterpret_cast<char4*>((isx ? g_x8 : g_w8) + (size_t)rr * 4096);
    #pragma unroll
    for (int j = 0; j < 4; j++) {
        char4 c;
        c.x = (char)__float2int_rn(v[j].x * inv);
        c.y = (char)__float2int_rn(v[j].y * inv);
        c.z = (char)__float2int_rn(v[j].z * inv);
        c.w = (char)__float2int_rn(v[j].w * inv);
        dst[threadIdx.x + 256 * j] = c;
    }
}

// ---------------- kernel 2: IMMA GEMM + fused epilogue ----------------
__global__ __launch_bounds__(512, 1) void gemm_pool_kernel(const float* __restrict__ bias) {
    extern __shared__ __align__(16) char dyn[];
    __shared__ float s_bias[BN];
    __shared__ float s_sw[BN];
    __shared__ float s_sx[BM];
    __shared__ float s_part[BM][4];

    const int tid = threadIdx.x;
    const int lane = tid & 31;
    const int wid = tid >> 5;           // 0..15
    const int wm = wid >> 2;            // m offset wm*64
    const int wn = wid & 3;             // n offset wn*32
    const int m0 = blockIdx.y * BM;
    const int n0 = blockIdx.x * BN;

    const uint32_t smem0 = s2u(dyn);

    if (tid < BN) { s_bias[tid] = bias[n0 + tid]; s_sw[tid] = g_sw[n0 + tid]; }
    if (tid < BM) s_sx[tid] = g_sx[m0 + tid];

    // ---- cp.async geometry (XOR swizzle: slot = chunk ^ (row&7), 16B chunks)
    const int  aR  = tid >> 1;
    const int  bR  = tid >> 2;
    const uint32_t aC = (uint32_t)(tid & 1) * 4u;
    const uint32_t bC = (uint32_t)(tid & 3) * 2u;
    const uint32_t ax = (uint32_t)(aR & 7);
    const uint32_t bx = (uint32_t)(bR & 7);
    const char* gA = (const char*)g_x8 + (size_t)(m0 + aR) * 4096;
    const char* gB = (const char*)g_w8 + (size_t)(n0 + bR) * 4096;
    const uint32_t aRow = smem0 + (uint32_t)aR * ROW_BYTES;
    const uint32_t bRow = smem0 + A_TILE + (uint32_t)bR * ROW_BYTES;

#define LOAD_CHUNK(i, s) do {                                                  \
        uint32_t _as = aRow + (uint32_t)(s) * STAGE;                           \
        uint32_t _bs = bRow + (uint32_t)(s) * STAGE;                           \
        const char* _ga = gA + (size_t)(i) * 128;                              \
        const char* _gb = gB + (size_t)(i) * 128;                              \
        _Pragma("unroll")                                                      \
        for (uint32_t c = 0; c < 4; c++)                                       \
            cp16(_as + (((aC + c) ^ ax) << 4), _ga + (aC + c) * 16);           \
        _Pragma("unroll")                                                      \
        for (uint32_t c = 0; c < 2; c++)                                       \
            cp16(_bs + (((bC + c) ^ bx) << 4), _gb + (bC + c) * 16);           \
        cp_commit();                                                           \
    } while (0)

    // ---- ldmatrix bases (byte-identical to the bf16 layout; ks = 32B k-chunk)
    uint32_t aAddr[4], bAddr[2], kOffA[4], kOffB[4];
    {
        const uint32_t al7 = (uint32_t)(lane & 7);
        const uint32_t ahi = (uint32_t)(lane >> 4);
        const uint32_t bcol = (uint32_t)((lane >> 3) & 1);
        const int arow = (lane & 15);
        const int brow = (lane & 7) + ((lane >> 4) << 3);
        #pragma unroll
        for (int mi = 0; mi < 4; mi++)
            aAddr[mi] = smem0 + (uint32_t)((wm * 64 + mi * 16 + arow) * ROW_BYTES);
        #pragma unroll
        for (int nj = 0; nj < 2; nj++)
            bAddr[nj] = smem0 + A_TILE
                        + (uint32_t)((wn * 32 + nj * 16 + brow) * ROW_BYTES);
        #pragma unroll
        for (uint32_t ks = 0; ks < 4; ks++) {
            kOffA[ks] = ((2u * ks + ahi) ^ al7) << 4;
            kOffB[ks] = ((2u * ks + bcol) ^ al7) << 4;
        }
    }

    int acc[4][4][4];
    #pragma unroll
    for (int mi = 0; mi < 4; mi++)
        #pragma unroll
        for (int ni = 0; ni < 4; ni++)
            #pragma unroll
            for (int k = 0; k < 4; k++) acc[mi][ni][k] = 0;

    // ---- prologue: 3 stages in flight
    LOAD_CHUNK(0, 0);
    LOAD_CHUNK(1, 1);
    LOAD_CHUNK(2, 2);

    #pragma unroll 1
    for (int i = 0; i < NITER; i++) {
        asm volatile("cp.async.wait_group 2;" ::: "memory");
        __syncthreads();

        if (i < NITER - 3) {
            LOAD_CHUNK(i + 3, (i + 3) & 3);   // stage != computing stage (i&3)
        } else {
            cp_commit();
        }

        const uint32_t so = (uint32_t)(i & 3) * STAGE;
        #pragma unroll
        for (int ks = 0; ks < 4; ks++) {
            uint32_t a[4][4], b[2][4];
            #pragma unroll
            for (int mi = 0; mi < 4; mi++)
                ldsm4(a[mi][0], a[mi][1], a[mi][2], a[mi][3],
                      aAddr[mi] + so + kOffA[ks]);
            #pragma unroll
            for (int nj = 0; nj < 2; nj++)
                ldsm4(b[nj][0], b[nj][1], b[nj][2], b[nj][3],
                      bAddr[nj] + so + kOffB[ks]);
            #pragma unroll
            for (int mi = 0; mi < 4; mi++)
                #pragma unroll
                for (int ni = 0; ni < 4; ni++)
                    imma16832(acc[mi][ni], a[mi], b[ni >> 1][(ni & 1) * 2],
                              b[ni >> 1][(ni & 1) * 2 + 1]);
        }
    }

    // ---- fused epilogue: dequant + bias + maxpool4 + row-sum via shuffles ----
    // acc[mi][ni][h*2+c] = row (wm*64+mi*16+(lane>>2)+h*8),
    //                      col (wn*32+ni*8+(lane&3)*2+c)
    {
        const int q = lane & 3;
        #pragma unroll
        for (int mi = 0; mi < 4; mi++)
            #pragma unroll
            for (int h = 0; h < 2; h++) {
                const int rl = wm * 64 + mi * 16 + (lane >> 2) + h * 8;
                const float sx = s_sx[rl];
                float s = 0.0f;
                #pragma unroll
                for (int ni = 0; ni < 4; ni++) {
                    const int c0 = wn * 32 + ni * 8 + q * 2;
                    float v0 = (float)acc[mi][ni][h * 2 + 0] * (sx * s_sw[c0 + 0])
                               + s_bias[c0 + 0];
                    float v1 = (float)acc[mi][ni][h * 2 + 1] * (sx * s_sw[c0 + 1])
                               + s_bias[c0 + 1];
                    float pm = fmaxf(v0, v1);
                    pm = fmaxf(pm, __shfl_xor_sync(0xFFFFFFFFu, pm, 1));
                    s += pm;                     // window (parity q>>1) of ni
                }
                s += __shfl_xor_sync(0xFFFFFFFFu, s, 2);   // other parity
                if (q == 0) s_part[rl][wn] = s;
            }
    }
    __syncthreads();
    if (tid < BM) {
        float4 v = *reinterpret_cast<const float4*>(&s_part[tid][0]);
        g_part[(size_t)(m0 + tid) * 32 + blockIdx.x] = (v.x + v.y) + (v.z + v.w);
    }
}

// ---------------- kernel 3: reduce 32 partials per row ----------------
__global__ __launch_bounds__(256) void reduce_kernel(float* __restrict__ out) {
    int r = blockIdx.x * 256 + threadIdx.x;
    const float4* p = reinterpret_cast<const float4*>(&g_part[(size_t)r * 32]);
    float s = 0.0f;
    #pragma unroll
    for (int i = 0; i < 8; i++) {
        float4 v = p[i];
        s += (v.x + v.y) + (v.z + v.w);
    }
    out[r] = 0.5f * s;
}

// ---------------- launch ----------------
extern "C" void kernel_launch(void* const* d_in, const int* in_sizes, int n_in,
                              void* d_out, int out_size) {
    const float4* x = (const float4*)d_in[0];
    const float4* w = (const float4*)d_in[1];
    const float*  b = (const float*)d_in[2];
    float* out = (float*)d_out;

    cudaFuncSetAttribute(gemm_pool_kernel,
                         cudaFuncAttributeMaxDynamicSharedMemorySize, DYN_SMEM);

    quantize_kernel<<<8192, 256>>>(x, w);
    gemm_pool_kernel<<<dim3(32, 16), 512, DYN_SMEM>>>(b);
    reduce_kernel<<<16, 256>>>(out);
}

// round 8
// speedup vs baseline: 3.0887x; 1.0654x over previous
#include <cuda_runtime.h>
#include <cstdint>

// ============================================================================
// out[m] = 0.5 * sum_w max_{j<4}( x[m,:].W[4w+j,:] + b[4w+j] )
// compute_100 PTX => legacy mma.sync. R7 (270.6us) saturated int8 IMMA
// (1024 MAC/cyc/SM) with 512 CTAs -> 3.46 waves (13% tail waste).
// R8: 128x128 CTA tiles, 1024 CTAs (6.92 waves, ~1% tail), 2 CTAs/SM
// (256 thr, 3-stage x 32KB = 96KB smem/CTA), cross-CTA bubble overlap.
// ============================================================================

__device__ int8_t g_x8[16777216];   // 16 MB
__device__ int8_t g_w8[16777216];   // 16 MB
__device__ float  g_sx[4096];
__device__ float  g_sw[4096];
__device__ float  g_part[131072];   // [4096 rows][32 n-tiles]

#define BM 128
#define BN 128
#define ROW_BYTES 128u
#define A_TILE (BM * ROW_BYTES)             // 16384
#define B_TILE (BN * ROW_BYTES)             // 16384
#define STAGE  (A_TILE + B_TILE)            // 32768
#define NSTAGE 3
#define DYN_SMEM (NSTAGE * STAGE)           // 98304
#define NITER 32                            // 4096 / 128

static __device__ __forceinline__ uint32_t s2u(const void* p) {
    uint32_t a;
    asm volatile("{ .reg .u64 t; cvta.to.shared.u64 t, %1; cvt.u32.u64 %0, t; }"
                 : "=r"(a) : "l"(p));
    return a;
}
static __device__ __forceinline__ void cp16(uint32_t dst, const void* src) {
    asm volatile("cp.async.cg.shared.global [%0], [%1], 16;"
                 :: "r"(dst), "l"(src) : "memory");
}
static __device__ __forceinline__ void cp_commit() {
    asm volatile("cp.async.commit_group;" ::: "memory");
}
static __device__ __forceinline__ void ldsm4(uint32_t& r0, uint32_t& r1,
                                             uint32_t& r2, uint32_t& r3, uint32_t a) {
    asm volatile("ldmatrix.sync.aligned.m8n8.x4.shared.b16 {%0,%1,%2,%3}, [%4];"
                 : "=r"(r0), "=r"(r1), "=r"(r2), "=r"(r3) : "r"(a));
}
static __device__ __forceinline__ void imma16832(int* c, const uint32_t* a,
                                                 uint32_t b0, uint32_t b1) {
    asm volatile("mma.sync.aligned.m16n8k32.row.col.s32.s8.s8.s32 "
                 "{%0,%1,%2,%3}, {%4,%5,%6,%7}, {%8,%9}, {%0,%1,%2,%3};"
                 : "+r"(c[0]), "+r"(c[1]), "+r"(c[2]), "+r"(c[3])
                 : "r"(a[0]), "r"(a[1]), "r"(a[2]), "r"(a[3]), "r"(b0), "r"(b1));
}

// ---------------- kernel 1: per-row absmax quantize ----------------
__global__ __launch_bounds__(256) void quantize_kernel(const float4* __restrict__ x,
                                                       const float4* __restrict__ w) {
    __shared__ float s_red[8];
    const int r = blockIdx.x;          // 0..8191: 0-4095 = x rows, rest = W rows
    const bool isx = r < 4096;
    const int rr = isx ? r : r - 4096;
    const float4* src = (isx ? x : w) + (size_t)rr * 1024;

    float4 v[4];
    float amax = 0.0f;
    #pragma unroll
    for (int j = 0; j < 4; j++) {
        v[j] = src[threadIdx.x + 256 * j];
        amax = fmaxf(amax, fmaxf(fmaxf(fabsf(v[j].x), fabsf(v[j].y)),
                                 fmaxf(fabsf(v[j].z), fabsf(v[j].w))));
    }
    #pragma unroll
    for (int o = 16; o; o >>= 1)
        amax = fmaxf(amax, __shfl_xor_sync(0xFFFFFFFFu, amax, o));
    if ((threadIdx.x & 31) == 0) s_red[threadIdx.x >> 5] = amax;
    __syncthreads();
    if (threadIdx.x < 32) {
        float m = (threadIdx.x < 8) ? s_red[threadIdx.x] : 0.0f;
        #pragma unroll
        for (int o = 4; o; o >>= 1)
            m = fmaxf(m, __shfl_xor_sync(0xFFFFFFFFu, m, o));
        if (threadIdx.x == 0) s_red[0] = m;
    }
    __syncthreads();
    const float smax = fmaxf(s_red[0], 1e-20f);
    const float inv = 127.0f / smax;
    if (threadIdx.x == 0) {
        if (isx) g_sx[rr] = smax * (1.0f / 127.0f);
        else     g_sw[rr] = smax * (1.0f / 127.0f);
    }
    char4* dst = reinterpret_cast<char4*>((isx ? g_x8 : g_w8) + (size_t)rr * 4096);
    #pragma unroll
    for (int j = 0; j < 4; j++) {
        char4 c;
        c.x = (char)__float2int_rn(v[j].x * inv);
        c.y = (char)__float2int_rn(v[j].y * inv);
        c.z = (char)__float2int_rn(v[j].z * inv);
        c.w = (char)__float2int_rn(v[j].w * inv);
        dst[threadIdx.x + 256 * j] = c;
    }
}

// ---------------- kernel 2: IMMA GEMM + fused epilogue ----------------
// 128x128 tile, 256 threads, 8 warps in 2x4 grid of 64x32 warp tiles.
__global__ __launch_bounds__(256, 2) void gemm_pool_kernel(const float* __restrict__ bias) {
    extern __shared__ __align__(16) char dyn[];
    __shared__ float s_bias[BN];
    __shared__ float s_sw[BN];
    __shared__ float s_sx[BM];
    __shared__ float s_part[BM][4];

    const int tid = threadIdx.x;
    const int lane = tid & 31;
    const int wid = tid >> 5;           // 0..7
    const int wm = wid >> 2;            // 0..1 -> m offset wm*64
    const int wn = wid & 3;             // 0..3 -> n offset wn*32
    const int m0 = blockIdx.y * BM;
    const int n0 = blockIdx.x * BN;

    const uint32_t smem0 = s2u(dyn);

    if (tid < BN) { s_bias[tid] = bias[n0 + tid]; s_sw[tid] = g_sw[n0 + tid]; }
    if (tid < BM) s_sx[tid] = g_sx[m0 + tid];

    // ---- cp.async geometry (XOR swizzle: slot = chunk ^ (row&7), 16B chunks)
    // thread t -> row t>>1 of A and of B, chunks (t&1)*4 .. +3 (4 each).
    const int  rR  = tid >> 1;                       // 0..127
    const uint32_t cC = (uint32_t)(tid & 1) * 4u;
    const uint32_t rx = (uint32_t)(rR & 7);
    const char* gA = (const char*)g_x8 + (size_t)(m0 + rR) * 4096;
    const char* gB = (const char*)g_w8 + (size_t)(n0 + rR) * 4096;
    const uint32_t aRow = smem0 + (uint32_t)rR * ROW_BYTES;
    const uint32_t bRow = smem0 + A_TILE + (uint32_t)rR * ROW_BYTES;

#define LOAD_CHUNK(i, s) do {                                                  \
        uint32_t _as = aRow + (uint32_t)(s) * STAGE;                           \
        uint32_t _bs = bRow + (uint32_t)(s) * STAGE;                           \
        const char* _ga = gA + (size_t)(i) * 128;                              \
        const char* _gb = gB + (size_t)(i) * 128;                              \
        _Pragma("unroll")                                                      \
        for (uint32_t c = 0; c < 4; c++)                                       \
            cp16(_as + (((cC + c) ^ rx) << 4), _ga + (cC + c) * 16);           \
        _Pragma("unroll")                                                      \
        for (uint32_t c = 0; c < 4; c++)                                       \
            cp16(_bs + (((cC + c) ^ rx) << 4), _gb + (cC + c) * 16);           \
        cp_commit();                                                           \
    } while (0)

    // ---- ldmatrix bases (identical fragment layout; ks = 32B k-chunk)
    uint32_t aAddr[4], bAddr[2], kOffA[4], kOffB[4];
    {
        const uint32_t al7 = (uint32_t)(lane & 7);
        const uint32_t ahi = (uint32_t)(lane >> 4);
        const uint32_t bcol = (uint32_t)((lane >> 3) & 1);
        const int arow = (lane & 15);
        const int brow = (lane & 7) + ((lane >> 4) << 3);
        #pragma unroll
        for (int mi = 0; mi < 4; mi++)
            aAddr[mi] = smem0 + (uint32_t)((wm * 64 + mi * 16 + arow) * ROW_BYTES);
        #pragma unroll
        for (int nj = 0; nj < 2; nj++)
            bAddr[nj] = smem0 + A_TILE
                        + (uint32_t)((wn * 32 + nj * 16 + brow) * ROW_BYTES);
        #pragma unroll
        for (uint32_t ks = 0; ks < 4; ks++) {
            kOffA[ks] = ((2u * ks + ahi) ^ al7) << 4;
            kOffB[ks] = ((2u * ks + bcol) ^ al7) << 4;
        }
    }

    int acc[4][4][4];
    #pragma unroll
    for (int mi = 0; mi < 4; mi++)
        #pragma unroll
        for (int ni = 0; ni < 4; ni++)
            #pragma unroll
            for (int k = 0; k < 4; k++) acc[mi][ni][k] = 0;

    // ---- prologue: 2 stages in flight (3-stage ring)
    LOAD_CHUNK(0, 0);
    LOAD_CHUNK(1, 1);

    #pragma unroll 1
    for (int i = 0; i < NITER; i++) {
        asm volatile("cp.async.wait_group 1;" ::: "memory");
        __syncthreads();

        if (i < NITER - 2) {
            int sp = i + 2;
            sp = (sp >= NSTAGE) ? (sp - ((sp / NSTAGE) * NSTAGE)) : sp;
            LOAD_CHUNK(i + 2, (i + 2) % NSTAGE);
        } else {
            cp_commit();
        }

        const uint32_t so = (uint32_t)(i % NSTAGE) * STAGE;
        #pragma unroll
        for (int ks = 0; ks < 4; ks++) {
            uint32_t a[4][4], b[2][4];
            #pragma unroll
            for (int mi = 0; mi < 4; mi++)
                ldsm4(a[mi][0], a[mi][1], a[mi][2], a[mi][3],
                      aAddr[mi] + so + kOffA[ks]);
            #pragma unroll
            for (int nj = 0; nj < 2; nj++)
                ldsm4(b[nj][0], b[nj][1], b[nj][2], b[nj][3],
                      bAddr[nj] + so + kOffB[ks]);
            #pragma unroll
            for (int mi = 0; mi < 4; mi++)
                #pragma unroll
                for (int ni = 0; ni < 4; ni++)
                    imma16832(acc[mi][ni], a[mi], b[ni >> 1][(ni & 1) * 2],
                              b[ni >> 1][(ni & 1) * 2 + 1]);
        }
    }

    // ---- fused epilogue: dequant + bias + maxpool4 + row-sum via shuffles ----
    // acc[mi][ni][h*2+c] = row (wm*64+mi*16+(lane>>2)+h*8),
    //                      col (wn*32+ni*8+(lane&3)*2+c)
    {
        const int q = lane & 3;
        #pragma unroll
        for (int mi = 0; mi < 4; mi++)
            #pragma unroll
            for (int h = 0; h < 2; h++) {
                const int rl = wm * 64 + mi * 16 + (lane >> 2) + h * 8;
                const float sx = s_sx[rl];
                float s = 0.0f;
                #pragma unroll
                for (int ni = 0; ni < 4; ni++) {
                    const int c0 = wn * 32 + ni * 8 + q * 2;
                    float v0 = (float)acc[mi][ni][h * 2 + 0] * (sx * s_sw[c0 + 0])
                               + s_bias[c0 + 0];
                    float v1 = (float)acc[mi][ni][h * 2 + 1] * (sx * s_sw[c0 + 1])
                               + s_bias[c0 + 1];
                    float pm = fmaxf(v0, v1);
                    pm = fmaxf(pm, __shfl_xor_sync(0xFFFFFFFFu, pm, 1));
                    s += pm;                     // window (parity q>>1) of ni
                }
                s += __shfl_xor_sync(0xFFFFFFFFu, s, 2);   // other parity
                if (q == 0) s_part[rl][wn] = s;
            }
    }
    __syncthreads();
    if (tid < BM) {
        float4 v = *reinterpret_cast<const float4*>(&s_part[tid][0]);
        g_part[(size_t)(m0 + tid) * 32 + blockIdx.x] = (v.x + v.y) + (v.z + v.w);
    }
}

// ---------------- kernel 3: reduce 32 partials per row ----------------
__global__ __launch_bounds__(256) void reduce_kernel(float* __restrict__ out) {
    int r = blockIdx.x * 256 + threadIdx.x;
    const float4* p = reinterpret_cast<const float4*>(&g_part[(size_t)r * 32]);
    float s = 0.0f;
    #pragma unroll
    for (int i = 0; i < 8; i++) {
        float4 v = p[i];
        s += (v.x + v.y) + (v.z + v.w);
    }
    out[r] = 0.5f * s;
}

// ---------------- launch ----------------
extern "C" void kernel_launch(void* const* d_in, const int* in_sizes, int n_in,
                              void* d_out, int out_size) {
    const float4* x = (const float4*)d_in[0];
    const float4* w = (const float4*)d_in[1];
    const float*  b = (const float*)d_in[2];
    float* out = (float*)d_out;

    cudaFuncSetAttribute(gemm_pool_kernel,
                         cudaFuncAttributeMaxDynamicSharedMemorySize, DYN_SMEM);

    quantize_kernel<<<8192, 256>>>(x, w);
    gemm_pool_kernel<<<dim3(32, 32), 256, DYN_SMEM>>>(b);
    reduce_kernel<<<16, 256>>>(out);
}